// round 15
// baseline (speedup 1.0000x reference)
#include <cuda_runtime.h>
#include <cstdint>

// Fixed problem shape
#define NPIX      102400            // B*H*W = 4*160*160
#define HW        25600             // H*W
#define NV        1024
#define OUT_ELEMS (NV * 2 * 32 * 32)   // 2,097,152 floats = 8 MB
#define NBLK      512               // 512 x 16KB TMA tiles = 8MB exactly
#define NPIXBLK   400               // blocks 0..399 own pixels (400*256 = NPIX)

// Gaussian in bin coordinates: t = (x+1)*16 - 0.5, sigma_bins = 0.8
#define CEXP   (-1.12710546f)
#define SKIPTH (4e-4f)

// Self-restoring state: zero at module load; last-finishing block restores
// g_sizes/g_done each launch -> deterministic across graph replays.
__device__ int      g_sizes[NV];
__device__ unsigned g_bar;
__device__ unsigned g_left;
__device__ unsigned g_done;

// ---------------------------------------------------------------------------
// Software grid barrier; all NBLK blocks co-resident:
// launch_bounds(256,4) -> <=64 regs -> 4 blocks/SM -> capacity 592 >= 512.
// ---------------------------------------------------------------------------
__device__ __forceinline__ void grid_barrier() {
    __syncthreads();
    if (threadIdx.x == 0) {
        __threadfence();
        atomicAdd(&g_bar, 1u);
        unsigned r;
        do {
            asm volatile("ld.acquire.gpu.global.u32 %0, [%1];"
                         : "=r"(r) : "l"(&g_bar));
        } while (r < NBLK);
        unsigned old = atomicAdd(&g_left, 1u);
        if (old == NBLK - 1) { g_bar = 0; g_left = 0; }
    }
    __syncthreads();
}

__device__ __forceinline__ void red4p(float gate, float* p,
                                      float a, float b, float c, float d) {
    asm volatile(
        "{\n\t"
        ".reg .pred pg;\n\t"
        "setp.gt.f32 pg, %0, %1;\n\t"
        "@pg red.global.add.v4.f32 [%2], {%3,%4,%5,%6};\n\t"
        "}"
        :: "f"(gate), "f"(SKIPTH), "l"(p), "f"(a), "f"(b), "f"(c), "f"(d)
        : "memory");
}

// ---------------------------------------------------------------------------
// Fused kernel:
//   issue async TMA zero (16KB/block) -> count + load inputs (TMA drains in
//   background) -> wait TMA -> grid barrier -> Parzen scatter -> restore.
// ---------------------------------------------------------------------------
__global__ void __launch_bounds__(256, 4)
fused_kernel(const int* __restrict__ seg,
             const int* __restrict__ byx,
             const float* __restrict__ grad,
             float* __restrict__ out) {
    __shared__ __align__(16) float zbuf[4096];          // 16 KB of zeros

    // stage zeros in smem and kick off the bulk store ASAP
    float4 z4 = make_float4(0.f, 0.f, 0.f, 0.f);
#pragma unroll
    for (int k = 0; k < 4; k++)
        reinterpret_cast<float4*>(zbuf)[threadIdx.x + k * 256] = z4;
    asm volatile("fence.proxy.async.shared::cta;" ::: "memory");
    __syncthreads();
    if (threadIdx.x == 0) {
        uint32_t src;
        asm("{ .reg .u64 t; cvta.to.shared.u64 t, %1; cvt.u32.u64 %0, t; }"
            : "=r"(src) : "l"(zbuf));
        float* dst = out + (size_t)blockIdx.x * 4096;
        asm volatile(
            "cp.async.bulk.global.shared::cta.bulk_group [%0], [%1], %2;\n\t"
            "cp.async.bulk.commit_group;\n\t"
            :: "l"(dst), "r"(src), "n"(16384) : "memory");
    }

    // pixel blocks: count + load/transform inputs while TMA drains
    bool haspix = blockIdx.x < NPIXBLK;
    int n = blockIdx.x * 256 + threadIdx.x;
    int v = 0;
    float t0 = 0.f, t1 = 0.f, t2 = 0.f, t3 = 0.f;
    if (haspix) {
        v = seg[n];
        atomicAdd(&g_sizes[v], 1);               // g_sizes pre-zeroed (self-restoring)
        t0 = (float)byx[NPIX + n]     * 0.2f - 0.5f;
        t1 = (float)byx[2 * NPIX + n] * 0.2f - 0.5f;
        int b  = n / HW;
        int hw = n - b * HW;
        t2 = grad[b * 2 * HW + hw]      * 16.f + 15.5f;
        t3 = grad[b * 2 * HW + HW + hw] * 16.f + 15.5f;
    }

    // TMA writes must be globally visible before any block's REDs
    if (threadIdx.x == 0) {
        asm volatile("cp.async.bulk.wait_group 0;" ::: "memory");
    }
    grid_barrier();                              // includes __threadfence()

    if (haspix) {
        float inv = 1.0f / (float)g_sizes[v];    // den = sizes*(P/32)^2 = sizes
        float* base0 = out + (size_t)v * 2048;

        // pair 0: dims (0,1) — always in range
        {
            int lo0 = min(26, max(0, __float2int_rd(t0) - 2));
            float w0[6];
#pragma unroll
            for (int k = 0; k < 6; k++) {
                float d = t0 - (float)(lo0 + k);
                w0[k] = exp2f(CEXP * d * d);
            }
            int qa1 = min(20, max(0, (__float2int_rd(t1) - 3) & ~3));
            float w1[12];
#pragma unroll
            for (int k = 0; k < 12; k++) {
                float d = t1 - (float)(qa1 + k);
                w1[k] = exp2f(CEXP * d * d);
            }
            float m0 = fmaxf(fmaxf(w1[0], w1[1]),  fmaxf(w1[2],  w1[3]));
            float m1 = fmaxf(fmaxf(w1[4], w1[5]),  fmaxf(w1[6],  w1[7]));
            float m2 = fmaxf(fmaxf(w1[8], w1[9]),  fmaxf(w1[10], w1[11]));
#pragma unroll
            for (int p = 0; p < 6; p++) {
                float wr = w0[p];
                float a  = wr * inv;
                float* row = base0 + (lo0 + p) * 32 + qa1;
                red4p(wr * m0, row,     a * w1[0], a * w1[1], a * w1[2],  a * w1[3]);
                red4p(wr * m1, row + 4, a * w1[4], a * w1[5], a * w1[6],  a * w1[7]);
                red4p(wr * m2, row + 8, a * w1[8], a * w1[9], a * w1[10], a * w1[11]);
            }
        }

        // pair 1: dims (2,3) — grads can fall outside all bins -> skip
        if (t2 > -3.5f && t2 < 34.5f && t3 > -3.5f && t3 < 34.5f) {
            int lo2 = min(26, max(0, __float2int_rd(t2) - 2));
            float w2[6];
#pragma unroll
            for (int k = 0; k < 6; k++) {
                float d = t2 - (float)(lo2 + k);
                w2[k] = exp2f(CEXP * d * d);
            }
            int qa3 = min(20, max(0, (__float2int_rd(t3) - 3) & ~3));
            float w3[12];
#pragma unroll
            for (int k = 0; k < 12; k++) {
                float d = t3 - (float)(qa3 + k);
                w3[k] = exp2f(CEXP * d * d);
            }
            float m0 = fmaxf(fmaxf(w3[0], w3[1]),  fmaxf(w3[2],  w3[3]));
            float m1 = fmaxf(fmaxf(w3[4], w3[5]),  fmaxf(w3[6],  w3[7]));
            float m2 = fmaxf(fmaxf(w3[8], w3[9]),  fmaxf(w3[10], w3[11]));
            float* base1 = base0 + 1024;
#pragma unroll
            for (int p = 0; p < 6; p++) {
                float wr = w2[p];
                float a  = wr * inv;
                float* row = base1 + (lo2 + p) * 32 + qa3;
                red4p(wr * m0, row,     a * w3[0], a * w3[1], a * w3[2],  a * w3[3]);
                red4p(wr * m1, row + 4, a * w3[4], a * w3[5], a * w3[6],  a * w3[7]);
                red4p(wr * m2, row + 8, a * w3[8], a * w3[9], a * w3[10], a * w3[11]);
            }
        }
    }

    // exit: last block restores g_sizes/g_done (no spinning; blocks increment
    // only after all their g_sizes reads are done)
    __syncthreads();
    __shared__ bool s_last;
    if (threadIdx.x == 0) {
        unsigned old = atomicAdd(&g_done, 1u);
        s_last = (old == NBLK - 1);
    }
    __syncthreads();
    if (s_last) {
#pragma unroll
        for (int i = threadIdx.x; i < NV; i += 256) g_sizes[i] = 0;
        if (threadIdx.x == 0) g_done = 0;
    }
}

// ---------------------------------------------------------------------------
extern "C" void kernel_launch(void* const* d_in, const int* in_sizes, int n_in,
                              void* d_out, int out_size) {
    const int*   seg  = (const int*)d_in[0];
    const int*   byx  = (const int*)d_in[1];
    const float* grad = (const float*)d_in[2];
    float*       out  = (float*)d_out;

    fused_kernel<<<NBLK, 256>>>(seg, byx, grad, out);
}

// round 16
// speedup vs baseline: 1.2453x; 1.2453x over previous
#include <cuda_runtime.h>
#include <cstdint>

// Fixed problem shape
#define NPIX      102400            // B*H*W = 4*160*160
#define HW        25600             // H*W
#define NV        1024
#define OUT_ELEMS (NV * 2 * 32 * 32)   // 2,097,152 floats = 8 MB = 512 x 16KB
#define NBLK      400               // 400 x 256 = NPIX exactly; 3/SM -> balanced

// Gaussian in bin coordinates: t = (x+1)*16 - 0.5, sigma_bins = 0.8
#define CEXP   (-1.12710546f)
#define SKIPTH (4e-4f)

// Self-restoring state: zero at module load; last-finishing block restores
// g_sizes/g_done each launch -> deterministic across graph replays.
__device__ int      g_sizes[NV];
__device__ unsigned g_bar;
__device__ unsigned g_left;
__device__ unsigned g_done;

// ---------------------------------------------------------------------------
// Software grid barrier; all 400 blocks co-resident (3/SM * 148 = 444 >= 400).
// ---------------------------------------------------------------------------
__device__ __forceinline__ void grid_barrier() {
    __syncthreads();
    if (threadIdx.x == 0) {
        __threadfence();
        atomicAdd(&g_bar, 1u);
        unsigned r;
        do {
            asm volatile("ld.acquire.gpu.global.u32 %0, [%1];"
                         : "=r"(r) : "l"(&g_bar));
        } while (r < NBLK);
        unsigned old = atomicAdd(&g_left, 1u);
        if (old == NBLK - 1) { g_bar = 0; g_left = 0; }
    }
    __syncthreads();
}

__device__ __forceinline__ void red4p(float gate, float* p,
                                      float a, float b, float c, float d) {
    asm volatile(
        "{\n\t"
        ".reg .pred pg;\n\t"
        "setp.gt.f32 pg, %0, %1;\n\t"
        "@pg red.global.add.v4.f32 [%2], {%3,%4,%5,%6};\n\t"
        "}"
        :: "f"(gate), "f"(SKIPTH), "l"(p), "f"(a), "f"(b), "f"(c), "f"(d)
        : "memory");
}

// ---------------------------------------------------------------------------
// Fused kernel, 400 blocks:
//   issue TMA zero tiles (1 per block + 2nd tile for blocks 0..111)
//   -> count + input loads (TMA drains in background)
//   -> wait TMA -> grid barrier -> Parzen scatter -> restore counters.
// ---------------------------------------------------------------------------
__global__ void __launch_bounds__(256, 3)
fused_kernel(const int* __restrict__ seg,
             const int* __restrict__ byx,
             const float* __restrict__ grad,
             float* __restrict__ out) {
    __shared__ __align__(16) float zbuf[4096];          // 16 KB of zeros

    // stage zeros in smem, kick off bulk store(s) ASAP
    float4 z4 = make_float4(0.f, 0.f, 0.f, 0.f);
#pragma unroll
    for (int k = 0; k < 4; k++)
        reinterpret_cast<float4*>(zbuf)[threadIdx.x + k * 256] = z4;
    asm volatile("fence.proxy.async.shared::cta;" ::: "memory");
    __syncthreads();
    if (threadIdx.x == 0) {
        uint32_t src;
        asm("{ .reg .u64 t; cvta.to.shared.u64 t, %1; cvt.u32.u64 %0, t; }"
            : "=r"(src) : "l"(zbuf));
        float* dst = out + (size_t)blockIdx.x * 4096;
        asm volatile(
            "cp.async.bulk.global.shared::cta.bulk_group [%0], [%1], %2;"
            :: "l"(dst), "r"(src), "n"(16384) : "memory");
        if (blockIdx.x < 112) {                          // tiles 400..511
            float* dst2 = out + (size_t)(NBLK + blockIdx.x) * 4096;
            asm volatile(
                "cp.async.bulk.global.shared::cta.bulk_group [%0], [%1], %2;"
                :: "l"(dst2), "r"(src), "n"(16384) : "memory");
        }
        asm volatile("cp.async.bulk.commit_group;" ::: "memory");
    }

    // count + load/transform inputs while TMA drains in background
    int n = blockIdx.x * 256 + threadIdx.x;              // 0..NPIX-1
    int v = seg[n];
    atomicAdd(&g_sizes[v], 1);                           // g_sizes pre-zeroed

    float t0 = (float)byx[NPIX + n]     * 0.2f - 0.5f;
    float t1 = (float)byx[2 * NPIX + n] * 0.2f - 0.5f;
    int   b  = n / HW;
    int   hw = n - b * HW;
    float t2 = grad[b * 2 * HW + hw]      * 16.f + 15.5f;
    float t3 = grad[b * 2 * HW + HW + hw] * 16.f + 15.5f;

    // TMA writes globally visible before any block's REDs
    if (threadIdx.x == 0)
        asm volatile("cp.async.bulk.wait_group 0;" ::: "memory");
    grid_barrier();                                      // includes threadfence

    // ---- Parzen scatter ----
    float inv = 1.0f / (float)g_sizes[v];                // den = sizes
    float* base0 = out + (size_t)v * 2048;

    // pair 0: dims (0,1) — always in range
    {
        int lo0 = min(26, max(0, __float2int_rd(t0) - 2));
        float w0[6];
#pragma unroll
        for (int k = 0; k < 6; k++) {
            float d = t0 - (float)(lo0 + k);
            w0[k] = exp2f(CEXP * d * d);
        }
        int qa1 = min(20, max(0, (__float2int_rd(t1) - 3) & ~3));
        float w1[12];
#pragma unroll
        for (int k = 0; k < 12; k++) {
            float d = t1 - (float)(qa1 + k);
            w1[k] = exp2f(CEXP * d * d);
        }
        float m0 = fmaxf(fmaxf(w1[0], w1[1]),  fmaxf(w1[2],  w1[3]));
        float m1 = fmaxf(fmaxf(w1[4], w1[5]),  fmaxf(w1[6],  w1[7]));
        float m2 = fmaxf(fmaxf(w1[8], w1[9]),  fmaxf(w1[10], w1[11]));
#pragma unroll
        for (int p = 0; p < 6; p++) {
            float wr = w0[p];
            float a  = wr * inv;
            float* row = base0 + (lo0 + p) * 32 + qa1;
            red4p(wr * m0, row,     a * w1[0], a * w1[1], a * w1[2],  a * w1[3]);
            red4p(wr * m1, row + 4, a * w1[4], a * w1[5], a * w1[6],  a * w1[7]);
            red4p(wr * m2, row + 8, a * w1[8], a * w1[9], a * w1[10], a * w1[11]);
        }
    }

    // pair 1: dims (2,3) — grads can fall outside all bins -> skip
    if (t2 > -3.5f && t2 < 34.5f && t3 > -3.5f && t3 < 34.5f) {
        int lo2 = min(26, max(0, __float2int_rd(t2) - 2));
        float w2[6];
#pragma unroll
        for (int k = 0; k < 6; k++) {
            float d = t2 - (float)(lo2 + k);
            w2[k] = exp2f(CEXP * d * d);
        }
        int qa3 = min(20, max(0, (__float2int_rd(t3) - 3) & ~3));
        float w3[12];
#pragma unroll
        for (int k = 0; k < 12; k++) {
            float d = t3 - (float)(qa3 + k);
            w3[k] = exp2f(CEXP * d * d);
        }
        float m0 = fmaxf(fmaxf(w3[0], w3[1]),  fmaxf(w3[2],  w3[3]));
        float m1 = fmaxf(fmaxf(w3[4], w3[5]),  fmaxf(w3[6],  w3[7]));
        float m2 = fmaxf(fmaxf(w3[8], w3[9]),  fmaxf(w3[10], w3[11]));
        float* base1 = base0 + 1024;
#pragma unroll
        for (int p = 0; p < 6; p++) {
            float wr = w2[p];
            float a  = wr * inv;
            float* row = base1 + (lo2 + p) * 32 + qa3;
            red4p(wr * m0, row,     a * w3[0], a * w3[1], a * w3[2],  a * w3[3]);
            red4p(wr * m1, row + 4, a * w3[4], a * w3[5], a * w3[6],  a * w3[7]);
            red4p(wr * m2, row + 8, a * w3[8], a * w3[9], a * w3[10], a * w3[11]);
        }
    }

    // exit: last block restores g_sizes/g_done (no spinning)
    __syncthreads();
    __shared__ bool s_last;
    if (threadIdx.x == 0) {
        unsigned old = atomicAdd(&g_done, 1u);
        s_last = (old == NBLK - 1);
    }
    __syncthreads();
    if (s_last) {
#pragma unroll
        for (int i = threadIdx.x; i < NV; i += 256) g_sizes[i] = 0;
        if (threadIdx.x == 0) g_done = 0;
    }
}

// ---------------------------------------------------------------------------
extern "C" void kernel_launch(void* const* d_in, const int* in_sizes, int n_in,
                              void* d_out, int out_size) {
    const int*   seg  = (const int*)d_in[0];
    const int*   byx  = (const int*)d_in[1];
    const float* grad = (const float*)d_in[2];
    float*       out  = (float*)d_out;

    fused_kernel<<<NBLK, 256>>>(seg, byx, grad, out);
}